// round 5
// baseline (speedup 1.0000x reference)
#include <cuda_runtime.h>
#include <cuda_bf16.h>
#include <cstdint>

// ---------------------------------------------------------------------------
// GIN_LCG on GB300. All activations kept as SPLIT bf16 (hi, lo) pairs;
// GEMMs via tcgen05 3-term bf16 split (Ah*Bh + Ah*Bl + Al*Bh), fp32 TMEM acc,
// N=256 per CTA (two N=128 MMA groups). Epilogues emit split bf16 and/or fp32.
// Edge scatter via red.global.add.v4.f32.
// Output layout: l_embs [5][L][256] then c_embs [5][C][256], fp32.
// ---------------------------------------------------------------------------

#if defined(__CUDA_ARCH_FEAT_SM103_ALL) || defined(__CUDA_ARCH_FEAT_SM100_ALL) || \
    defined(__CUDA_ARCH_FEAT_SM101_ALL) || defined(__CUDA_ARCH_FEAT_SM110_ALL)
#define HAS_TC 1
#else
#define HAS_TC 0
#endif

#define DD 256
#define PAD_L 100096
#define PAD_C 50048

typedef __nv_bfloat16 bf16;

// -------------------- device scratch (no allocs allowed) -------------------
// split bf16 activations
__device__ bf16 g_lh [(size_t)PAD_L * DD]; __device__ bf16 g_ll [(size_t)PAD_L * DD];
__device__ bf16 g_ch [(size_t)PAD_C * DD]; __device__ bf16 g_cl [(size_t)PAD_C * DD];
__device__ bf16 g_hh [(size_t)PAD_L * DD]; __device__ bf16 g_hl [(size_t)PAD_L * DD];
__device__ bf16 g_2h [(size_t)PAD_L * DD]; __device__ bf16 g_2l [(size_t)PAD_L * DD];
__device__ bf16 g_alh[(size_t)PAD_L * DD]; __device__ bf16 g_all[(size_t)PAD_L * DD];
__device__ bf16 g_ach[(size_t)PAD_C * DD]; __device__ bf16 g_acl[(size_t)PAD_C * DD];
// fp32 scratch
__device__ float g_lmsg[(size_t)PAD_L * DD];
__device__ float g_cmsg[(size_t)PAD_C * DD];
__device__ float g_aggl[(size_t)PAD_L * DD];
__device__ float g_aggc[(size_t)PAD_C * DD];
// transposed split weights: [N=256, K] bf16, hi and lo
__device__ bf16 g_wth[851968];
__device__ bf16 g_wtl[851968];

// -------------------- PTX helpers ------------------------------------------
__device__ __forceinline__ uint32_t smem_u32(const void* p) {
    uint32_t a;
    asm("{ .reg .u64 t; cvta.to.shared.u64 t, %1; cvt.u32.u64 %0, t; }"
        : "=r"(a) : "l"(p));
    return a;
}

#define FENCE_ASYNC()     asm volatile("fence.proxy.async.shared::cta;" ::: "memory")
#define MBAR_INIT(a, c) \
    asm volatile("mbarrier.init.shared.b64 [%0], %1;" :: "r"(a), "r"((uint32_t)(c)) : "memory")
#define MBAR_INVAL(a) \
    asm volatile("mbarrier.inval.shared.b64 [%0];" :: "r"(a) : "memory")
#define MBAR_WAIT(addr, ph) do {                                               \
    uint32_t _m = (addr); uint32_t _p = (ph);                                  \
    asm volatile("{\n\t.reg .pred P;\n\tWL_%=:\n\t"                            \
        "mbarrier.try_wait.parity.acquire.cta.shared::cta.b64 P, [%0], %1, 0x989680;\n\t" \
        "@P bra.uni WD_%=;\n\tbra.uni WL_%=;\n\tWD_%=:\n\t}"                   \
        :: "r"(_m), "r"(_p) : "memory");                                       \
} while (0)

#if HAS_TC
#define TC_ALLOC(sa, n) \
    asm volatile("tcgen05.alloc.cta_group::1.sync.aligned.shared::cta.b32 [%0], %1;" \
                 :: "r"(sa), "r"((uint32_t)(n)) : "memory")
#define TC_DEALLOC(t, n) \
    asm volatile("tcgen05.dealloc.cta_group::1.sync.aligned.b32 %0, %1;" \
                 :: "r"(t), "r"((uint32_t)(n)))
#define TC_RELINQ() \
    asm volatile("tcgen05.relinquish_alloc_permit.cta_group::1.sync.aligned;")
#define TC_COMMIT(mb) \
    asm volatile("tcgen05.commit.cta_group::1.mbarrier::arrive::one.shared::cluster.b64 [%0];" \
                 :: "r"(mb) : "memory")
#define TC_FENCE_AFTER()  asm volatile("tcgen05.fence::after_thread_sync;" ::: "memory")
#define TC_FENCE_BEFORE() asm volatile("tcgen05.fence::before_thread_sync;" ::: "memory")
#define TC_WAIT_LD()      asm volatile("tcgen05.wait::ld.sync.aligned;" ::: "memory")

#define TC_LD_X32(r, ta)                                                       \
    asm volatile("tcgen05.ld.sync.aligned.32x32b.x32.b32 "                     \
        "{%0, %1, %2, %3, %4, %5, %6, %7, "                                    \
        " %8, %9, %10, %11, %12, %13, %14, %15, "                              \
        " %16, %17, %18, %19, %20, %21, %22, %23, "                            \
        " %24, %25, %26, %27, %28, %29, %30, %31}, [%32];"                     \
        : "=r"((r)[0]),  "=r"((r)[1]),  "=r"((r)[2]),  "=r"((r)[3]),           \
          "=r"((r)[4]),  "=r"((r)[5]),  "=r"((r)[6]),  "=r"((r)[7]),           \
          "=r"((r)[8]),  "=r"((r)[9]),  "=r"((r)[10]), "=r"((r)[11]),          \
          "=r"((r)[12]), "=r"((r)[13]), "=r"((r)[14]), "=r"((r)[15]),          \
          "=r"((r)[16]), "=r"((r)[17]), "=r"((r)[18]), "=r"((r)[19]),          \
          "=r"((r)[20]), "=r"((r)[21]), "=r"((r)[22]), "=r"((r)[23]),          \
          "=r"((r)[24]), "=r"((r)[25]), "=r"((r)[26]), "=r"((r)[27]),          \
          "=r"((r)[28]), "=r"((r)[29]), "=r"((r)[30]), "=r"((r)[31])           \
        : "r"(ta))

__device__ __forceinline__ uint64_t smem_desc(uint32_t addr) {
    // SW128 K-major: layout=2, version=1(Blackwell), SBO=64, LBO=1
    const uint64_t base = (uint64_t(2) << 61) | (uint64_t(1) << 46) |
                          (uint64_t(64) << 32) | (uint64_t(1) << 16);
    return base | ((uint64_t)(addr >> 4) & 0x3FFF);
}
__device__ __forceinline__ void mma_f16_ss(uint32_t d, uint64_t ad, uint64_t bd,
                                           uint32_t idesc, bool accum) {
    uint32_t en = accum ? 1u : 0u;
    asm volatile(
        "{\n\t.reg .pred p;\n\tsetp.ne.u32 p, %5, 0;\n\t"
        "tcgen05.mma.cta_group::1.kind::f16 [%0], %1, %2, %3, {%4, %4, %4, %4}, p;\n\t}"
        :: "r"(d), "l"(ad), "l"(bd), "r"(idesc), "r"(0u), "r"(en) : "memory");
}
#endif  // HAS_TC

#define SW128(o) ((o) ^ ((((uint32_t)(o)) >> 3) & 0x70))

// idesc: dtype=F32, atype=btype=BF16, N=128, M=128 (cg1)  [R4-proven]
static constexpr uint32_t IDESC =
    (1u << 4) | (1u << 7) | (1u << 10) | ((128u / 8) << 17) | ((128u / 16) << 24);

// stage: Ah 16K | Al 16K | Bh 32K | Bl 32K  = 96KB ; 2 stages
#define A_T         16384
#define B_T         32768
#define STAGE_BYTES (2 * A_T + 2 * B_T)
#define SMEM_TOTAL  (1024 + 2 * STAGE_BYTES)

struct GemmParams {
    const bf16 *A0h, *A0l, *A1h, *A1l, *A2h, *A2l;  // [M,256] row-major K-segments
    const bf16 *Wh, *Wl;                             // [256, K]
    const float* bias;
    float* C;                                        // optional fp32 out [M,256]
    bf16 *Ch, *Cl;                                   // optional split bf16 out
    int M, K, row_xor, relu;
};

__device__ __forceinline__ uint32_t pkbf(bf16 a, bf16 b) {
    __nv_bfloat162 t(a, b);
    return *reinterpret_cast<uint32_t*>(&t);
}

#if HAS_TC
// copy one stage's A(hi|lo) + B(hi,lo) tiles to smem (bf16, SW128)
__device__ __forceinline__ void produce_stage(
    const GemmParams& p, char* tilep, uint32_t sb, int s,
    int arow_idx, int tid, int wait_cnt) {

    const int buf = s & 1;
    char* tb = tilep + buf * STAGE_BYTES;
    const int k0  = s * 64;
    const int seg = k0 >> 8;
    const bf16* Ah = (seg == 0) ? p.A0h : ((seg == 1) ? p.A1h : p.A2h);
    const bf16* Al = (seg == 0) ? p.A0l : ((seg == 1) ? p.A1l : p.A2l);
    const int kc   = k0 & 255;
    const int r    = tid >> 1;      // 0..127  (A row within tile)
    const int part = tid & 1;       // 0 = hi, 1 = lo

    const bf16* asrc = (part ? Al : Ah) + (size_t)arow_idx * DD + kc;
    uint4 av[8];
    #pragma unroll
    for (int j = 0; j < 8; j++) av[j] = __ldg((const uint4*)asrc + j);

    const int n = tid;              // 0..255  (B row = output col)
    const bf16* bh = p.Wh + (size_t)n * p.K + k0;
    const bf16* bl = p.Wl + (size_t)n * p.K + k0;
    uint4 bhv[8], blv[8];
    #pragma unroll
    for (int j = 0; j < 8; j++) bhv[j] = __ldg((const uint4*)bh + j);
    #pragma unroll
    for (int j = 0; j < 8; j++) blv[j] = __ldg((const uint4*)bl + j);

    if (wait_cnt > 0)
        MBAR_WAIT(sb + (buf ? 16 : 8), (uint32_t)((wait_cnt - 1) & 1));

    #pragma unroll
    for (int j = 0; j < 8; j++) {
        const uint32_t so = SW128((uint32_t)(r * 128 + j * 16));
        *(uint4*)(tb + part * A_T + so) = av[j];
    }
    #pragma unroll
    for (int j = 0; j < 8; j++) {
        const uint32_t so = SW128((uint32_t)(n * 128 + j * 16));
        *(uint4*)(tb + 2 * A_T + so)       = bhv[j];
        *(uint4*)(tb + 2 * A_T + B_T + so) = blv[j];
    }
    FENCE_ASYNC();
}
#endif  // HAS_TC

__global__ __launch_bounds__(256, 1)
void gemm_tc(GemmParams p) {
#if HAS_TC
    extern __shared__ char smem[];
    const uint32_t sb = smem_u32(smem);
    const uint32_t tbase = (sb + 32 + 1023u) & ~1023u;
    char* tilep = smem + (tbase - sb);
    const int tid = threadIdx.x;
    const int wid = tid >> 5, lid = tid & 31;
    const int rowBase = blockIdx.x * 128;
    const int nst = p.K / 64;

    if (wid == 0) TC_ALLOC(sb, 512);
    if (tid == 0) { MBAR_INIT(sb + 8, 1); MBAR_INIT(sb + 16, 1); }
    __syncthreads();
    uint32_t tmem;
    asm volatile("ld.shared.b32 %0, [%1];" : "=r"(tmem) : "r"(sb));

    const int arow_idx = (rowBase + (tid >> 1)) ^ p.row_xor;  // padded buffers: no clamp

    int cnt[2] = {0, 0};
    produce_stage(p, tilep, sb, 0, arow_idx, tid, 0);
    __syncthreads();

    for (int s = 0; s < nst; s++) {
        const int buf = s & 1;
        if (tid == 0) {
            const uint32_t tb = tbase + buf * STAGE_BYTES;
            const uint64_t dah = smem_desc(tb);
            const uint64_t dal = smem_desc(tb + A_T);
            const uint64_t dbh = smem_desc(tb + 2 * A_T);
            const uint64_t dbl = smem_desc(tb + 2 * A_T + B_T);
            #pragma unroll
            for (int n = 0; n < 2; n++) {
                const uint32_t d  = tmem + n * 128;
                const uint64_t bh = dbh + n * 1024;   // 128 rows * 128B / 16
                const uint64_t bl = dbl + n * 1024;
                #pragma unroll
                for (int sub = 0; sub < 4; sub++) {
                    const bool first = (s == 0 && sub == 0);
                    mma_f16_ss(d, dah + sub * 2, bh + sub * 2, IDESC, !first);
                    mma_f16_ss(d, dah + sub * 2, bl + sub * 2, IDESC, true);
                    mma_f16_ss(d, dal + sub * 2, bh + sub * 2, IDESC, true);
                }
            }
            TC_COMMIT(sb + (buf ? 16 : 8));
        }
        cnt[buf]++;

        if (s + 1 < nst) {
            produce_stage(p, tilep, sb, s + 1, arow_idx, tid, cnt[(s + 1) & 1]);
            __syncthreads();
        }
    }

    {
        const int lb = (nst - 1) & 1, ob = lb ^ 1;
        MBAR_WAIT(sb + (lb ? 16 : 8), (uint32_t)((cnt[lb] - 1) & 1));
        if (cnt[ob] > 0)
            MBAR_WAIT(sb + (ob ? 16 : 8), (uint32_t)((cnt[ob] - 1) & 1));
    }
    TC_FENCE_AFTER();

    if (wid < 4) {
        const int rr = rowBase + wid * 32 + lid;
        const bool v = rr < p.M;
        float* crow = p.C  ? p.C  + (size_t)rr * DD : nullptr;
        bf16*  hrow = p.Ch ? p.Ch + (size_t)rr * DD : nullptr;
        bf16*  lrow = p.Cl ? p.Cl + (size_t)rr * DD : nullptr;
        #pragma unroll
        for (int ch = 0; ch < 8; ch++) {
            uint32_t dr[32];
            TC_LD_X32(dr, tmem + ch * 32);
            TC_WAIT_LD();
            if (v) {
                #pragma unroll
                for (int j = 0; j < 8; j++) {
                    const int c = ch * 32 + j * 4;
                    float4 o;
                    o.x = __uint_as_float(dr[j * 4 + 0]) + __ldg(&p.bias[c + 0]);
                    o.y = __uint_as_float(dr[j * 4 + 1]) + __ldg(&p.bias[c + 1]);
                    o.z = __uint_as_float(dr[j * 4 + 2]) + __ldg(&p.bias[c + 2]);
                    o.w = __uint_as_float(dr[j * 4 + 3]) + __ldg(&p.bias[c + 3]);
                    if (p.relu) {
                        o.x = fmaxf(o.x, 0.f); o.y = fmaxf(o.y, 0.f);
                        o.z = fmaxf(o.z, 0.f); o.w = fmaxf(o.w, 0.f);
                    }
                    if (crow) *(float4*)(crow + c) = o;
                    if (hrow) {
                        bf16 h0 = __float2bfloat16_rn(o.x);
                        bf16 h1 = __float2bfloat16_rn(o.y);
                        bf16 h2 = __float2bfloat16_rn(o.z);
                        bf16 h3 = __float2bfloat16_rn(o.w);
                        uint2 hv, lv;
                        hv.x = pkbf(h0, h1); hv.y = pkbf(h2, h3);
                        lv.x = pkbf(__float2bfloat16_rn(o.x - __bfloat162float(h0)),
                                    __float2bfloat16_rn(o.y - __bfloat162float(h1)));
                        lv.y = pkbf(__float2bfloat16_rn(o.z - __bfloat162float(h2)),
                                    __float2bfloat16_rn(o.w - __bfloat162float(h3)));
                        *(uint2*)(hrow + c) = hv;
                        *(uint2*)(lrow + c) = lv;
                    }
                }
            }
        }
        TC_FENCE_BEFORE();
    }

    __syncthreads();
    if (tid == 0) { MBAR_INVAL(sb + 8); MBAR_INVAL(sb + 16); }
    __syncthreads();
    if (wid == 0) { TC_RELINQ(); TC_DEALLOC(tmem, 512); }

#else  // ---------------- fp32 SIMT fallback (base-arch cubin; safety) -------
    __shared__ float As[16][132];
    __shared__ float Bs[16][128];
    const int tid = threadIdx.x;
    const int tx  = tid & 15;
    const int ty  = tid >> 4;
    const int rowBase = blockIdx.x * 128;

    for (int nh = 0; nh < 2; nh++) {
        const int colBase = nh * 128;
        float acc[8][8];
        #pragma unroll
        for (int i = 0; i < 8; i++)
            #pragma unroll
            for (int j = 0; j < 8; j++) acc[i][j] = 0.f;

        const int nt = p.K / 16;
        const int a_row = tid >> 2, a_c4 = tid & 3;
        const int b_n = tid >> 1, b_h = tid & 1;

        for (int t = 0; t < nt; t++) {
            const int k0 = t * 16, seg = k0 >> 8;
            const bf16* Ah = (seg == 0) ? p.A0h : ((seg == 1) ? p.A1h : p.A2h);
            const bf16* Al = (seg == 0) ? p.A0l : ((seg == 1) ? p.A1l : p.A2l);
            const int kcol = (k0 & 255) + a_c4 * 4;
            #pragma unroll
            for (int i = 0; i < 2; i++) {
                const int r = rowBase + a_row + i * 64;
                const size_t ro = (size_t)((r < p.M ? r : 0) ^ p.row_xor) * DD + kcol;
                #pragma unroll
                for (int q = 0; q < 4; q++)
                    As[a_c4 * 4 + q][a_row + i * 64] =
                        (r < p.M) ? __bfloat162float(Ah[ro + q]) +
                                    __bfloat162float(Al[ro + q]) : 0.f;
            }
            {
                const size_t wo = (size_t)(colBase + b_n) * p.K + k0 + b_h * 8;
                #pragma unroll
                for (int j = 0; j < 8; j++)
                    Bs[b_h * 8 + j][b_n] = __bfloat162float(p.Wh[wo + j]) +
                                           __bfloat162float(p.Wl[wo + j]);
            }
            __syncthreads();
            #pragma unroll
            for (int k = 0; k < 16; k++) {
                float a[8], b[8];
                #pragma unroll
                for (int i = 0; i < 8; i++) a[i] = As[k][ty * 8 + i];
                #pragma unroll
                for (int j = 0; j < 8; j++) b[j] = Bs[k][tx * 8 + j];
                #pragma unroll
                for (int i = 0; i < 8; i++)
                    #pragma unroll
                    for (int j = 0; j < 8; j++)
                        acc[i][j] = fmaf(a[i], b[j], acc[i][j]);
            }
            __syncthreads();
        }

        const int col = colBase + tx * 8;
        #pragma unroll
        for (int i = 0; i < 8; i++) {
            const int r = rowBase + ty * 8 + i;
            if (r >= p.M) break;
            #pragma unroll
            for (int j = 0; j < 8; j++) {
                float o = acc[i][j] + p.bias[col + j];
                if (p.relu) o = fmaxf(o, 0.f);
                if (p.C) p.C[(size_t)r * DD + col + j] = o;
                if (p.Ch) {
                    bf16 h = __float2bfloat16_rn(o);
                    p.Ch[(size_t)r * DD + col + j] = h;
                    p.Cl[(size_t)r * DD + col + j] =
                        __float2bfloat16_rn(o - __bfloat162float(h));
                }
            }
        }
        __syncthreads();
    }
#endif
}

// -------------------- weight transpose + bf16 split ------------------------
__global__ void wsplit_kernel(const float* __restrict__ W,
                              bf16* __restrict__ oh, bf16* __restrict__ ol,
                              int K, int N) {
    const int idx = blockIdx.x * blockDim.x + threadIdx.x;
    if (idx >= K * N) return;
    const int n = idx / K;
    const int k = idx - n * K;
    const float x = W[(size_t)k * N + n];
    const bf16 hi = __float2bfloat16_rn(x);
    oh[idx] = hi;
    ol[idx] = __float2bfloat16_rn(x - __bfloat162float(hi));
}

// -------------------- fp32 -> split bf16 (elementwise) ---------------------
__global__ void split_kernel(const float4* __restrict__ in,
                             uint2* __restrict__ oh, uint2* __restrict__ ol,
                             int n4) {
    const int i = blockIdx.x * blockDim.x + threadIdx.x;
    if (i >= n4) return;
    const float4 v = __ldg(&in[i]);
    const bf16 h0 = __float2bfloat16_rn(v.x);
    const bf16 h1 = __float2bfloat16_rn(v.y);
    const bf16 h2 = __float2bfloat16_rn(v.z);
    const bf16 h3 = __float2bfloat16_rn(v.w);
    uint2 hv, lv;
    __nv_bfloat162 a(h0, h1), b(h2, h3);
    hv.x = *reinterpret_cast<uint32_t*>(&a);
    hv.y = *reinterpret_cast<uint32_t*>(&b);
    __nv_bfloat162 c(__float2bfloat16_rn(v.x - __bfloat162float(h0)),
                     __float2bfloat16_rn(v.y - __bfloat162float(h1)));
    __nv_bfloat162 d(__float2bfloat16_rn(v.z - __bfloat162float(h2)),
                     __float2bfloat16_rn(v.w - __bfloat162float(h3)));
    lv.x = *reinterpret_cast<uint32_t*>(&c);
    lv.y = *reinterpret_cast<uint32_t*>(&d);
    oh[i] = hv;
    ol[i] = lv;
}

// -------------------- fused gather + segment-sum over edges ----------------
__global__ void scatter_add_kernel(const float4* __restrict__ msg,
                                   const int* __restrict__ src,
                                   const int* __restrict__ dst,
                                   float4* __restrict__ aggr, int E) {
    int t = blockIdx.x * blockDim.x + threadIdx.x;
    const int total = E * (DD / 4);
    if (t >= total) return;
    const int e = t >> 6;
    const int c = t & 63;
    const int s = __ldg(&src[e]);
    const int d = __ldg(&dst[e]);
    float4 v = __ldg(&msg[(size_t)s * 64 + c]);
    float4* p = &aggr[(size_t)d * 64 + c];
    asm volatile("red.global.add.v4.f32 [%0], {%1, %2, %3, %4};"
                 :: "l"(p), "f"(v.x), "f"(v.y), "f"(v.z), "f"(v.w)
                 : "memory");
}

// -------------------- host orchestration -----------------------------------
static void run_gemm(const bf16* A0h, const bf16* A0l,
                     const bf16* A1h, const bf16* A1l,
                     const bf16* A2h, const bf16* A2l,
                     const bf16* Wh, const bf16* Wl, const float* bias,
                     float* C, bf16* Ch, bf16* Cl,
                     int M, int K, int row_xor, int relu) {
    GemmParams p;
    p.A0h = A0h; p.A0l = A0l; p.A1h = A1h; p.A1l = A1l; p.A2h = A2h; p.A2l = A2l;
    p.Wh = Wh; p.Wl = Wl; p.bias = bias;
    p.C = C; p.Ch = Ch; p.Cl = Cl;
    p.M = M; p.K = K; p.row_xor = row_xor; p.relu = relu;
    gemm_tc<<<(M + 127) / 128, 256, SMEM_TOTAL>>>(p);
}

extern "C" void kernel_launch(void* const* d_in, const int* in_sizes, int n_in,
                              void* d_out, int out_size) {
    const int off = n_in - 24;
    const int*   l_edge = (const int*)  d_in[off + 0];
    const int*   c_edge = (const int*)  d_in[off + 1];
    const float* l_emb0 = (const float*)d_in[off + 2];
    const float* c_emb0 = (const float*)d_in[off + 3];
    const float* w[20];
    for (int i = 0; i < 20; i++) w[i] = (const float*)d_in[off + 4 + i];
    // w[0..3]=l2c, w[4..7]=c2l, w[8..11]=l2l, w[12..15]=cu, w[16..19]=lu

    const int E   = in_sizes[off + 0];
    const int Lsz = in_sizes[off + 2] / DD;
    const int Csz = in_sizes[off + 3] / DD;

    bf16 *lh, *ll, *chb, *clb, *hh, *hl, *t2h, *t2l, *alh, *all_, *ach, *acl;
    cudaGetSymbolAddress((void**)&lh,  g_lh);  cudaGetSymbolAddress((void**)&ll,  g_ll);
    cudaGetSymbolAddress((void**)&chb, g_ch);  cudaGetSymbolAddress((void**)&clb, g_cl);
    cudaGetSymbolAddress((void**)&hh,  g_hh);  cudaGetSymbolAddress((void**)&hl,  g_hl);
    cudaGetSymbolAddress((void**)&t2h, g_2h);  cudaGetSymbolAddress((void**)&t2l, g_2l);
    cudaGetSymbolAddress((void**)&alh, g_alh); cudaGetSymbolAddress((void**)&all_, g_all);
    cudaGetSymbolAddress((void**)&ach, g_ach); cudaGetSymbolAddress((void**)&acl, g_acl);
    float *lmsg, *cmsg, *aggl, *aggc;
    cudaGetSymbolAddress((void**)&lmsg, g_lmsg);
    cudaGetSymbolAddress((void**)&cmsg, g_cmsg);
    cudaGetSymbolAddress((void**)&aggl, g_aggl);
    cudaGetSymbolAddress((void**)&aggc, g_aggc);
    bf16 *wth, *wtl;
    cudaGetSymbolAddress((void**)&wth, g_wth);
    cudaGetSymbolAddress((void**)&wtl, g_wtl);

    cudaFuncSetAttribute(gemm_tc, cudaFuncAttributeMaxDynamicSharedMemorySize,
                         SMEM_TOTAL);

    // transpose + split the 10 weight matrices into bf16 hi/lo [256, K]
    static const size_t woff[10] = {0, 65536, 131072, 196608, 262144, 327680,
                                    393216, 524288, 589824, 786432};
    static const int    wKs [10] = {256, 256, 256, 256, 256, 256, 512, 256, 768, 256};
    static const int    wsrc[10] = {0, 2, 4, 6, 8, 10, 12, 14, 16, 18};
    for (int i = 0; i < 10; i++) {
        const int total = wKs[i] * 256;
        wsplit_kernel<<<(total + 255) / 256, 256>>>(w[wsrc[i]], wth + woff[i],
                                                    wtl + woff[i], wKs[i], 256);
    }

    float* out = (float*)d_out;
    float* l_out[5];
    float* c_out[5];
    for (int t = 0; t < 5; t++) {
        l_out[t] = out + (size_t)t * Lsz * DD;
        c_out[t] = out + (size_t)5 * Lsz * DD + (size_t)t * Csz * DD;
    }

    cudaMemcpyAsync(l_out[0], l_emb0, (size_t)Lsz * DD * sizeof(float),
                    cudaMemcpyDeviceToDevice, 0);
    cudaMemcpyAsync(c_out[0], c_emb0, (size_t)Csz * DD * sizeof(float),
                    cudaMemcpyDeviceToDevice, 0);

    const int Ln4 = Lsz * DD / 4, Cn4 = Csz * DD / 4;
    split_kernel<<<(Ln4 + 255) / 256, 256>>>((const float4*)l_emb0,
                                             (uint2*)lh, (uint2*)ll, Ln4);
    split_kernel<<<(Cn4 + 255) / 256, 256>>>((const float4*)c_emb0,
                                             (uint2*)chb, (uint2*)clb, Cn4);

    const int scat_total  = E * (DD / 4);
    const int scat_blocks = (scat_total + 255) / 256;

    #define WH(i) (wth + woff[i])
    #define WL(i) (wtl + woff[i])
    #define NB    (const bf16*)nullptr

    for (int t = 0; t < 4; t++) {
        // l2c message features: hid = relu(l W1 + b1); lmsg = hid W2 + b2
        run_gemm(lh, ll, NB, NB, NB, NB, WH(0), WL(0), w[1],
                 nullptr, hh, hl, Lsz, 256, 0, 1);
        run_gemm(hh, hl, NB, NB, NB, NB, WH(1), WL(1), w[3],
                 lmsg, nullptr, nullptr, Lsz, 256, 0, 0);

        // c2l message features
        run_gemm(chb, clb, NB, NB, NB, NB, WH(2), WL(2), w[5],
                 nullptr, hh, hl, Csz, 256, 0, 1);
        run_gemm(hh, hl, NB, NB, NB, NB, WH(3), WL(3), w[7],
                 cmsg, nullptr, nullptr, Csz, 256, 0, 0);

        // l2l: MLP(flip(l)); flip fused via row^1
        run_gemm(lh, ll, NB, NB, NB, NB, WH(4), WL(4), w[9],
                 nullptr, hh, hl, Lsz, 256, 1, 1);
        run_gemm(hh, hl, NB, NB, NB, NB, WH(5), WL(5), w[11],
                 nullptr, t2h, t2l, Lsz, 256, 0, 0);

        // clause update
        cudaMemsetAsync(aggc, 0, (size_t)Csz * DD * sizeof(float), 0);
        scatter_add_kernel<<<scat_blocks, 256>>>((const float4*)lmsg, l_edge,
                                                 c_edge, (float4*)aggc, E);
        split_kernel<<<(Cn4 + 255) / 256, 256>>>((const float4*)aggc,
                                                 (uint2*)ach, (uint2*)acl, Cn4);
        run_gemm(chb, clb, ach, acl, NB, NB, WH(6), WL(6), w[13],
                 nullptr, hh, hl, Csz, 512, 0, 1);
        run_gemm(hh, hl, NB, NB, NB, NB, WH(7), WL(7), w[15],
                 c_out[t + 1], chb, clb, Csz, 256, 0, 0);

        // literal update
        cudaMemsetAsync(aggl, 0, (size_t)Lsz * DD * sizeof(float), 0);
        scatter_add_kernel<<<scat_blocks, 256>>>((const float4*)cmsg, c_edge,
                                                 l_edge, (float4*)aggl, E);
        split_kernel<<<(Ln4 + 255) / 256, 256>>>((const float4*)aggl,
                                                 (uint2*)alh, (uint2*)all_, Ln4);
        run_gemm(lh, ll, alh, all_, t2h, t2l, WH(8), WL(8), w[17],
                 nullptr, hh, hl, Lsz, 768, 0, 1);
        run_gemm(hh, hl, NB, NB, NB, NB, WH(9), WL(9), w[19],
                 l_out[t + 1], lh, ll, Lsz, 256, 0, 0);
    }
    #undef WH
    #undef WL
    #undef NB
}

// round 7
// speedup vs baseline: 1.4255x; 1.4255x over previous
#include <cuda_runtime.h>
#include <cuda_bf16.h>
#include <cstdint>

// ---------------------------------------------------------------------------
// GIN_LCG on GB300. Split-bf16 activations; tcgen05 3-term bf16 GEMMs with
// fp32 TMEM accumulation; N=256 per CTA. R6/R7: warp-coalesced tile producers
// (8 lanes per 128B row-slice -> nL=4 per LDG instead of 32).
// Output layout: l_embs [5][L][256] then c_embs [5][C][256], fp32.
// ---------------------------------------------------------------------------

#if defined(__CUDA_ARCH_FEAT_SM103_ALL) || defined(__CUDA_ARCH_FEAT_SM100_ALL) || \
    defined(__CUDA_ARCH_FEAT_SM101_ALL) || defined(__CUDA_ARCH_FEAT_SM110_ALL)
#define HAS_TC 1
#else
#define HAS_TC 0
#endif

#define DD 256
#define PAD_L 100096
#define PAD_C 50048

typedef __nv_bfloat16 bf16;

// -------------------- device scratch (no allocs allowed) -------------------
__device__ bf16 g_lh [(size_t)PAD_L * DD]; __device__ bf16 g_ll [(size_t)PAD_L * DD];
__device__ bf16 g_ch [(size_t)PAD_C * DD]; __device__ bf16 g_cl [(size_t)PAD_C * DD];
__device__ bf16 g_hh [(size_t)PAD_L * DD]; __device__ bf16 g_hl [(size_t)PAD_L * DD];
__device__ bf16 g_2h [(size_t)PAD_L * DD]; __device__ bf16 g_2l [(size_t)PAD_L * DD];
__device__ bf16 g_alh[(size_t)PAD_L * DD]; __device__ bf16 g_all[(size_t)PAD_L * DD];
__device__ bf16 g_ach[(size_t)PAD_C * DD]; __device__ bf16 g_acl[(size_t)PAD_C * DD];
__device__ float g_lmsg[(size_t)PAD_L * DD];
__device__ float g_cmsg[(size_t)PAD_C * DD];
__device__ float g_aggl[(size_t)PAD_L * DD];
__device__ float g_aggc[(size_t)PAD_C * DD];
__device__ bf16 g_wth[851968];
__device__ bf16 g_wtl[851968];

// -------------------- PTX helpers ------------------------------------------
__device__ __forceinline__ uint32_t smem_u32(const void* p) {
    uint32_t a;
    asm("{ .reg .u64 t; cvta.to.shared.u64 t, %1; cvt.u32.u64 %0, t; }"
        : "=r"(a) : "l"(p));
    return a;
}

#define FENCE_ASYNC()     asm volatile("fence.proxy.async.shared::cta;" ::: "memory")
#define MBAR_INIT(a, c) \
    asm volatile("mbarrier.init.shared.b64 [%0], %1;" :: "r"(a), "r"((uint32_t)(c)) : "memory")
#define MBAR_INVAL(a) \
    asm volatile("mbarrier.inval.shared.b64 [%0];" :: "r"(a) : "memory")
#define MBAR_WAIT(addr, ph) do {                                               \
    uint32_t _m = (addr); uint32_t _p = (ph);                                  \
    asm volatile("{\n\t.reg .pred P;\n\tWL_%=:\n\t"                            \
        "mbarrier.try_wait.parity.acquire.cta.shared::cta.b64 P, [%0], %1, 0x989680;\n\t" \
        "@P bra.uni WD_%=;\n\tbra.uni WL_%=;\n\tWD_%=:\n\t}"                   \
        :: "r"(_m), "r"(_p) : "memory");                                       \
} while (0)

#if HAS_TC
#define TC_ALLOC(sa, n) \
    asm volatile("tcgen05.alloc.cta_group::1.sync.aligned.shared::cta.b32 [%0], %1;" \
                 :: "r"(sa), "r"((uint32_t)(n)) : "memory")
#define TC_DEALLOC(t, n) \
    asm volatile("tcgen05.dealloc.cta_group::1.sync.aligned.b32 %0, %1;" \
                 :: "r"(t), "r"((uint32_t)(n)))
#define TC_RELINQ() \
    asm volatile("tcgen05.relinquish_alloc_permit.cta_group::1.sync.aligned;")
#define TC_COMMIT(mb) \
    asm volatile("tcgen05.commit.cta_group::1.mbarrier::arrive::one.shared::cluster.b64 [%0];" \
                 :: "r"(mb) : "memory")
#define TC_FENCE_AFTER()  asm volatile("tcgen05.fence::after_thread_sync;" ::: "memory")
#define TC_FENCE_BEFORE() asm volatile("tcgen05.fence::before_thread_sync;" ::: "memory")
#define TC_WAIT_LD()      asm volatile("tcgen05.wait::ld.sync.aligned;" ::: "memory")

#define TC_LD_X32(r, ta)                                                       \
    asm volatile("tcgen05.ld.sync.aligned.32x32b.x32.b32 "                     \
        "{%0, %1, %2, %3, %4, %5, %6, %7, "                                    \
        " %8, %9, %10, %11, %12, %13, %14, %15, "                              \
        " %16, %17, %18, %19, %20, %21, %22, %23, "                            \
        " %24, %25, %26, %27, %28, %29, %30, %31}, [%32];"                     \
        : "=r"((r)[0]),  "=r"((r)[1]),  "=r"((r)[2]),  "=r"((r)[3]),           \
          "=r"((r)[4]),  "=r"((r)[5]),  "=r"((r)[6]),  "=r"((r)[7]),           \
          "=r"((r)[8]),  "=r"((r)[9]),  "=r"((r)[10]), "=r"((r)[11]),          \
          "=r"((r)[12]), "=r"((r)[13]), "=r"((r)[14]), "=r"((r)[15]),          \
          "=r"((r)[16]), "=r"((r)[17]), "=r"((r)[18]), "=r"((r)[19]),          \
          "=r"((r)[20]), "=r"((r)[21]), "=r"((r)[22]), "=r"((r)[23]),          \
          "=r"((r)[24]), "=r"((r)[25]), "=r"((r)[26]), "=r"((r)[27]),          \
          "=r"((r)[28]), "=r"((r)[29]), "=r"((r)[30]), "=r"((r)[31])           \
        : "r"(ta))

__device__ __forceinline__ uint64_t smem_desc(uint32_t addr) {
    // SW128 K-major: layout=2, version=1(Blackwell), SBO=64, LBO=1
    const uint64_t base = (uint64_t(2) << 61) | (uint64_t(1) << 46) |
                          (uint64_t(64) << 32) | (uint64_t(1) << 16);
    return base | ((uint64_t)(addr >> 4) & 0x3FFF);
}
__device__ __forceinline__ void mma_f16_ss(uint32_t d, uint64_t ad, uint64_t bd,
                                           uint32_t idesc, bool accum) {
    uint32_t en = accum ? 1u : 0u;
    asm volatile(
        "{\n\t.reg .pred p;\n\tsetp.ne.u32 p, %5, 0;\n\t"
        "tcgen05.mma.cta_group::1.kind::f16 [%0], %1, %2, %3, {%4, %4, %4, %4}, p;\n\t}"
        :: "r"(d), "l"(ad), "l"(bd), "r"(idesc), "r"(0u), "r"(en) : "memory");
}
#endif  // HAS_TC

#define SW128(o) ((o) ^ ((((uint32_t)(o)) >> 3) & 0x70))

// idesc: dtype=F32, atype=btype=BF16, N=128, M=128 (cg1)  [R4-proven]
static constexpr uint32_t IDESC =
    (1u << 4) | (1u << 7) | (1u << 10) | ((128u / 8) << 17) | ((128u / 16) << 24);

// stage: Ah 16K | Al 16K | Bh 32K | Bl 32K  = 96KB ; 2 stages
#define A_T         16384
#define B_T         32768
#define STAGE_BYTES (2 * A_T + 2 * B_T)
#define SMEM_TOTAL  (1024 + 2 * STAGE_BYTES)

struct GemmParams {
    const bf16 *A0h, *A0l, *A1h, *A1l, *A2h, *A2l;  // [M,256] row-major K-segments
    const bf16 *Wh, *Wl;                             // [256, K]
    const float* bias;
    float* C;                                        // optional fp32 out
    bf16 *Ch, *Cl;                                   // optional split bf16 out
    int M, K, row_xor, relu;
};

__device__ __forceinline__ uint32_t pkbf(bf16 a, bf16 b) {
    __nv_bfloat162 t(a, b);
    return *reinterpret_cast<uint32_t*>(&t);
}

#if HAS_TC
// Warp-coalesced stage producer: 8 consecutive lanes cover one 128B row-slice.
__device__ __forceinline__ void produce_stage(
    const GemmParams& p, char* tilep, uint32_t sb, int s,
    int rowBase, int tid, int wait_cnt) {

    const int buf = s & 1;
    char* tb = tilep + buf * STAGE_BYTES;
    const int k0  = s * 64;
    const int seg = k0 >> 8;
    const bf16* Ah = (seg == 0) ? p.A0h : ((seg == 1) ? p.A1h : p.A2h);
    const bf16* Al = (seg == 0) ? p.A0l : ((seg == 1) ? p.A1l : p.A2l);
    const int kc = k0 & 255;

    // A: 128 rows x 64 k-elems (128B) per part; 1024 16B-units; 4 per thread.
    uint4 avh[4], avl[4];
    #pragma unroll
    for (int it = 0; it < 4; it++) {
        const int idx = tid + it * 256;
        const int r = idx >> 3, j = idx & 7;
        const size_t go = (size_t)((rowBase + r) ^ p.row_xor) * DD + kc + j * 8;
        avh[it] = __ldg((const uint4*)(Ah + go));
        avl[it] = __ldg((const uint4*)(Al + go));
    }
    // B: 256 rows x 64 k-elems per part; 2048 16B-units; 8 per thread.
    uint4 bvh[8], bvl[8];
    #pragma unroll
    for (int it = 0; it < 8; it++) {
        const int idx = tid + it * 256;
        const int n = idx >> 3, j = idx & 7;
        const size_t go = (size_t)n * p.K + k0 + j * 8;
        bvh[it] = __ldg((const uint4*)(p.Wh + go));
        bvl[it] = __ldg((const uint4*)(p.Wl + go));
    }

    if (wait_cnt > 0)
        MBAR_WAIT(sb + (buf ? 16 : 8), (uint32_t)((wait_cnt - 1) & 1));

    #pragma unroll
    for (int it = 0; it < 4; it++) {
        const int idx = tid + it * 256;
        const int r = idx >> 3, j = idx & 7;
        const uint32_t so = SW128((uint32_t)(r * 128 + j * 16));
        *(uint4*)(tb + so)       = avh[it];
        *(uint4*)(tb + A_T + so) = avl[it];
    }
    #pragma unroll
    for (int it = 0; it < 8; it++) {
        const int idx = tid + it * 256;
        const int n = idx >> 3, j = idx & 7;
        const uint32_t so = SW128((uint32_t)(n * 128 + j * 16));
        *(uint4*)(tb + 2 * A_T + so)       = bvh[it];
        *(uint4*)(tb + 2 * A_T + B_T + so) = bvl[it];
    }
    FENCE_ASYNC();
}
#endif  // HAS_TC

__global__ __launch_bounds__(256, 1)
void gemm_tc(GemmParams p) {
#if HAS_TC
    extern __shared__ char smem[];
    const uint32_t sb = smem_u32(smem);
    const uint32_t tbase = (sb + 32 + 1023u) & ~1023u;
    char* tilep = smem + (tbase - sb);
    const int tid = threadIdx.x;
    const int wid = tid >> 5, lid = tid & 31;
    const int rowBase = blockIdx.x * 128;
    const int nst = p.K / 64;

    if (wid == 0) TC_ALLOC(sb, 512);
    if (tid == 0) { MBAR_INIT(sb + 8, 1); MBAR_INIT(sb + 16, 1); }
    __syncthreads();
    uint32_t tmem;
    asm volatile("ld.shared.b32 %0, [%1];" : "=r"(tmem) : "r"(sb));

    int cnt[2] = {0, 0};
    produce_stage(p, tilep, sb, 0, rowBase, tid, 0);
    __syncthreads();

    for (int s = 0; s < nst; s++) {
        const int buf = s & 1;
        if (tid == 0) {
            const uint32_t tb = tbase + buf * STAGE_BYTES;
            const uint64_t dah = smem_desc(tb);
            const uint64_t dal = smem_desc(tb + A_T);
            const uint64_t dbh = smem_desc(tb + 2 * A_T);
            const uint64_t dbl = smem_desc(tb + 2 * A_T + B_T);
            #pragma unroll
            for (int n = 0; n < 2; n++) {
                const uint32_t d  = tmem + n * 128;
                const uint64_t bh = dbh + n * 1024;   // 128 rows * 128B / 16
                const uint64_t bl = dbl + n * 1024;
                #pragma unroll
                for (int sub = 0; sub < 4; sub++) {
                    const bool first = (s == 0 && sub == 0);
                    mma_f16_ss(d, dah + sub * 2, bh + sub * 2, IDESC, !first);
                    mma_f16_ss(d, dah + sub * 2, bl + sub * 2, IDESC, true);
                    mma_f16_ss(d, dal + sub * 2, bh + sub * 2, IDESC, true);
                }
            }
            TC_COMMIT(sb + (buf ? 16 : 8));
        }
        cnt[buf]++;

        if (s + 1 < nst) {
            produce_stage(p, tilep, sb, s + 1, rowBase, tid, cnt[(s + 1) & 1]);
            __syncthreads();
        }
    }

    {
        const int lb = (nst - 1) & 1, ob = lb ^ 1;
        MBAR_WAIT(sb + (lb ? 16 : 8), (uint32_t)((cnt[lb] - 1) & 1));
        if (cnt[ob] > 0)
            MBAR_WAIT(sb + (ob ? 16 : 8), (uint32_t)((cnt[ob] - 1) & 1));
    }
    TC_FENCE_AFTER();

    if (wid < 4) {
        const int rr = rowBase + wid * 32 + lid;
        const bool v = rr < p.M;
        float* crow = p.C  ? p.C  + (size_t)rr * DD : nullptr;
        bf16*  hrow = p.Ch ? p.Ch + (size_t)rr * DD : nullptr;
        bf16*  lrow = p.Cl ? p.Cl + (size_t)rr * DD : nullptr;
        #pragma unroll
        for (int ch = 0; ch < 8; ch++) {
            uint32_t dr[32];
            TC_LD_X32(dr, tmem + ch * 32);
            TC_WAIT_LD();
            if (v) {
                #pragma unroll
                for (int j = 0; j < 8; j++) {
                    const int c = ch * 32 + j * 4;
                    float4 o;
                    o.x = __uint_as_float(dr[j * 4 + 0]) + __ldg(&p.bias[c + 0]);
                    o.y = __uint_as_float(dr[j * 4 + 1]) + __ldg(&p.bias[c + 1]);
                    o.z = __uint_as_float(dr[j * 4 + 2]) + __ldg(&p.bias[c + 2]);
                    o.w = __uint_as_float(dr[j * 4 + 3]) + __ldg(&p.bias[c + 3]);
                    if (p.relu) {
                        o.x = fmaxf(o.x, 0.f); o.y = fmaxf(o.y, 0.f);
                        o.z = fmaxf(o.z, 0.f); o.w = fmaxf(o.w, 0.f);
                    }
                    if (crow) *(float4*)(crow + c) = o;
                    if (hrow) {
                        bf16 h0 = __float2bfloat16_rn(o.x);
                        bf16 h1 = __float2bfloat16_rn(o.y);
                        bf16 h2 = __float2bfloat16_rn(o.z);
                        bf16 h3 = __float2bfloat16_rn(o.w);
                        uint2 hv, lv;
                        hv.x = pkbf(h0, h1); hv.y = pkbf(h2, h3);
                        lv.x = pkbf(__float2bfloat16_rn(o.x - __bfloat162float(h0)),
                                    __float2bfloat16_rn(o.y - __bfloat162float(h1)));
                        lv.y = pkbf(__float2bfloat16_rn(o.z - __bfloat162float(h2)),
                                    __float2bfloat16_rn(o.w - __bfloat162float(h3)));
                        *(uint2*)(hrow + c) = hv;
                        *(uint2*)(lrow + c) = lv;
                    }
                }
            }
        }
        TC_FENCE_BEFORE();
    }

    __syncthreads();
    if (tid == 0) { MBAR_INVAL(sb + 8); MBAR_INVAL(sb + 16); }
    __syncthreads();
    if (wid == 0) { TC_RELINQ(); TC_DEALLOC(tmem, 512); }

#else  // ---------------- fp32 SIMT fallback (base-arch cubin; safety) -------
    __shared__ float As[16][132];
    __shared__ float Bs[16][128];
    const int tid = threadIdx.x;
    const int tx  = tid & 15;
    const int ty  = tid >> 4;
    const int rowBase = blockIdx.x * 128;

    for (int nh = 0; nh < 2; nh++) {
        const int colBase = nh * 128;
        float acc[8][8];
        #pragma unroll
        for (int i = 0; i < 8; i++)
            #pragma unroll
            for (int j = 0; j < 8; j++) acc[i][j] = 0.f;

        const int nt = p.K / 16;
        const int a_row = tid >> 2, a_c4 = tid & 3;
        const int b_n = tid >> 1, b_h = tid & 1;

        for (int t = 0; t < nt; t++) {
            const int k0 = t * 16, seg = k0 >> 8;
            const bf16* Ah = (seg == 0) ? p.A0h : ((seg == 1) ? p.A1h : p.A2h);
            const bf16* Al = (seg == 0) ? p.A0l : ((seg == 1) ? p.A1l : p.A2l);
            const int kcol = (k0 & 255) + a_c4 * 4;
            #pragma unroll
            for (int i = 0; i < 2; i++) {
                const int r = rowBase + a_row + i * 64;
                const size_t ro = (size_t)((r < p.M ? r : 0) ^ p.row_xor) * DD + kcol;
                #pragma unroll
                for (int q = 0; q < 4; q++)
                    As[a_c4 * 4 + q][a_row + i * 64] =
                        (r < p.M) ? __bfloat162float(Ah[ro + q]) +
                                    __bfloat162float(Al[ro + q]) : 0.f;
            }
            {
                const size_t wo = (size_t)(colBase + b_n) * p.K + k0 + b_h * 8;
                #pragma unroll
                for (int j = 0; j < 8; j++)
                    Bs[b_h * 8 + j][b_n] = __bfloat162float(p.Wh[wo + j]) +
                                           __bfloat162float(p.Wl[wo + j]);
            }
            __syncthreads();
            #pragma unroll
            for (int k = 0; k < 16; k++) {
                float a[8], b[8];
                #pragma unroll
                for (int i = 0; i < 8; i++) a[i] = As[k][ty * 8 + i];
                #pragma unroll
                for (int j = 0; j < 8; j++) b[j] = Bs[k][tx * 8 + j];
                #pragma unroll
                for (int i = 0; i < 8; i++)
                    #pragma unroll
                    for (int j = 0; j < 8; j++)
                        acc[i][j] = fmaf(a[i], b[j], acc[i][j]);
            }
            __syncthreads();
        }

        const int col = colBase + tx * 8;
        #pragma unroll
        for (int i = 0; i < 8; i++) {
            const int r = rowBase + ty * 8 + i;
            if (r >= p.M) break;
            #pragma unroll
            for (int j = 0; j < 8; j++) {
                float o = acc[i][j] + p.bias[col + j];
                if (p.relu) o = fmaxf(o, 0.f);
                if (p.C) p.C[(size_t)r * DD + col + j] = o;
                if (p.Ch) {
                    bf16 h = __float2bfloat16_rn(o);
                    p.Ch[(size_t)r * DD + col + j] = h;
                    p.Cl[(size_t)r * DD + col + j] =
                        __float2bfloat16_rn(o - __bfloat162float(h));
                }
            }
        }
        __syncthreads();
    }
#endif
}

// -------------------- weight transpose + bf16 split ------------------------
__global__ void wsplit_kernel(const float* __restrict__ W,
                              bf16* __restrict__ oh, bf16* __restrict__ ol,
                              int K, int N) {
    const int idx = blockIdx.x * blockDim.x + threadIdx.x;
    if (idx >= K * N) return;
    const int n = idx / K;
    const int k = idx - n * K;
    const float x = W[(size_t)k * N + n];
    const bf16 hi = __float2bfloat16_rn(x);
    oh[idx] = hi;
    ol[idx] = __float2bfloat16_rn(x - __bfloat162float(hi));
}

// -------------------- fp32 -> split bf16 (elementwise) ---------------------
__global__ void split_kernel(const float4* __restrict__ in,
                             uint2* __restrict__ oh, uint2* __restrict__ ol,
                             int n4) {
    const int i = blockIdx.x * blockDim.x + threadIdx.x;
    if (i >= n4) return;
    const float4 v = __ldg(&in[i]);
    const bf16 h0 = __float2bfloat16_rn(v.x);
    const bf16 h1 = __float2bfloat16_rn(v.y);
    const bf16 h2 = __float2bfloat16_rn(v.z);
    const bf16 h3 = __float2bfloat16_rn(v.w);
    uint2 hv, lv;
    __nv_bfloat162 a(h0, h1), b(h2, h3);
    hv.x = *reinterpret_cast<uint32_t*>(&a);
    hv.y = *reinterpret_cast<uint32_t*>(&b);
    __nv_bfloat162 c(__float2bfloat16_rn(v.x - __bfloat162float(h0)),
                     __float2bfloat16_rn(v.y - __bfloat162float(h1)));
    __nv_bfloat162 d(__float2bfloat16_rn(v.z - __bfloat162float(h2)),
                     __float2bfloat16_rn(v.w - __bfloat162float(h3)));
    lv.x = *reinterpret_cast<uint32_t*>(&c);
    lv.y = *reinterpret_cast<uint32_t*>(&d);
    oh[i] = hv;
    ol[i] = lv;
}

// -------------------- fused gather + segment-sum over edges ----------------
__global__ void scatter_add_kernel(const float4* __restrict__ msg,
                                   const int* __restrict__ src,
                                   const int* __restrict__ dst,
                                   float4* __restrict__ aggr, int E) {
    int t = blockIdx.x * blockDim.x + threadIdx.x;
    const int total = E * (DD / 4);
    if (t >= total) return;
    const int e = t >> 6;
    const int c = t & 63;
    const int s = __ldg(&src[e]);
    const int d = __ldg(&dst[e]);
    float4 v = __ldg(&msg[(size_t)s * 64 + c]);
    float4* p = &aggr[(size_t)d * 64 + c];
    asm volatile("red.global.add.v4.f32 [%0], {%1, %2, %3, %4};"
                 :: "l"(p), "f"(v.x), "f"(v.y), "f"(v.z), "f"(v.w)
                 : "memory");
}

// -------------------- host orchestration -----------------------------------
static void run_gemm(const bf16* A0h, const bf16* A0l,
                     const bf16* A1h, const bf16* A1l,
                     const bf16* A2h, const bf16* A2l,
                     const bf16* Wh, const bf16* Wl, const float* bias,
                     float* C, bf16* Ch, bf16* Cl,
                     int M, int K, int row_xor, int relu) {
    GemmParams p;
    p.A0h = A0h; p.A0l = A0l; p.A1h = A1h; p.A1l = A1l; p.A2h = A2h; p.A2l = A2l;
    p.Wh = Wh; p.Wl = Wl; p.bias = bias;
    p.C = C; p.Ch = Ch; p.Cl = Cl;
    p.M = M; p.K = K; p.row_xor = row_xor; p.relu = relu;
    gemm_tc<<<(M + 127) / 128, 256, SMEM_TOTAL>>>(p);
}

extern "C" void kernel_launch(void* const* d_in, const int* in_sizes, int n_in,
                              void* d_out, int out_size) {
    const int off = n_in - 24;
    const int*   l_edge = (const int*)  d_in[off + 0];
    const int*   c_edge = (const int*)  d_in[off + 1];
    const float* l_emb0 = (const float*)d_in[off + 2];
    const float* c_emb0 = (const float*)d_in[off + 3];
    const float* w[20];
    for (int i = 0; i < 20; i++) w[i] = (const float*)d_in[off + 4 + i];
    // w[0..3]=l2c, w[4..7]=c2l, w[8..11]=l2l, w[12..15]=cu, w[16..19]=lu

    const int E   = in_sizes[off + 0];
    const int Lsz = in_sizes[off + 2] / DD;
    const int Csz = in_sizes[off + 3] / DD;

    bf16 *lh, *ll, *chb, *clb, *hh, *hl, *t2h, *t2l, *alh, *all_, *ach, *acl;
    cudaGetSymbolAddress((void**)&lh,  g_lh);  cudaGetSymbolAddress((void**)&ll,  g_ll);
    cudaGetSymbolAddress((void**)&chb, g_ch);  cudaGetSymbolAddress((void**)&clb, g_cl);
    cudaGetSymbolAddress((void**)&hh,  g_hh);  cudaGetSymbolAddress((void**)&hl,  g_hl);
    cudaGetSymbolAddress((void**)&t2h, g_2h);  cudaGetSymbolAddress((void**)&t2l, g_2l);
    cudaGetSymbolAddress((void**)&alh, g_alh); cudaGetSymbolAddress((void**)&all_, g_all);
    cudaGetSymbolAddress((void**)&ach, g_ach); cudaGetSymbolAddress((void**)&acl, g_acl);
    float *lmsg, *cmsg, *aggl, *aggc;
    cudaGetSymbolAddress((void**)&lmsg, g_lmsg);
    cudaGetSymbolAddress((void**)&cmsg, g_cmsg);
    cudaGetSymbolAddress((void**)&aggl, g_aggl);
    cudaGetSymbolAddress((void**)&aggc, g_aggc);
    bf16 *wth, *wtl;
    cudaGetSymbolAddress((void**)&wth, g_wth);
    cudaGetSymbolAddress((void**)&wtl, g_wtl);

    cudaFuncSetAttribute(gemm_tc, cudaFuncAttributeMaxDynamicSharedMemorySize,
                         SMEM_TOTAL);

    // transpose + split the 10 weight matrices into bf16 hi/lo [256, K]
    static const size_t woff[10] = {0, 65536, 131072, 196608, 262144, 327680,
                                    393216, 524288, 589824, 786432};
    static const int    wKs [10] = {256, 256, 256, 256, 256, 256, 512, 256, 768, 256};
    static const int    wsrc[10] = {0, 2, 4, 6, 8, 10, 12, 14, 16, 18};
    for (int i = 0; i < 10; i++) {
        const int total = wKs[i] * 256;
        wsplit_kernel<<<(total + 255) / 256, 256>>>(w[wsrc[i]], wth + woff[i],
                                                    wtl + woff[i], wKs[i], 256);
    }

    float* out = (float*)d_out;
    float* l_out[5];
    float* c_out[5];
    for (int t = 0; t < 5; t++) {
        l_out[t] = out + (size_t)t * Lsz * DD;
        c_out[t] = out + (size_t)5 * Lsz * DD + (size_t)t * Csz * DD;
    }

    cudaMemcpyAsync(l_out[0], l_emb0, (size_t)Lsz * DD * sizeof(float),
                    cudaMemcpyDeviceToDevice, 0);
    cudaMemcpyAsync(c_out[0], c_emb0, (size_t)Csz * DD * sizeof(float),
                    cudaMemcpyDeviceToDevice, 0);

    const int Ln4 = Lsz * DD / 4, Cn4 = Csz * DD / 4;
    split_kernel<<<(Ln4 + 255) / 256, 256>>>((const float4*)l_emb0,
                                             (uint2*)lh, (uint2*)ll, Ln4);
    split_kernel<<<(Cn4 + 255) / 256, 256>>>((const float4*)c_emb0,
                                             (uint2*)chb, (uint2*)clb, Cn4);

    const int scat_total  = E * (DD / 4);
    const int scat_blocks = (scat_total + 255) / 256;

    #define WH(i) (wth + woff[i])
    #define WL(i) (wtl + woff[i])
    #define NB    (const bf16*)nullptr

    for (int t = 0; t < 4; t++) {
        // l2c message features
        run_gemm(lh, ll, NB, NB, NB, NB, WH(0), WL(0), w[1],
                 nullptr, hh, hl, Lsz, 256, 0, 1);
        run_gemm(hh, hl, NB, NB, NB, NB, WH(1), WL(1), w[3],
                 lmsg, nullptr, nullptr, Lsz, 256, 0, 0);

        // c2l message features
        run_gemm(chb, clb, NB, NB, NB, NB, WH(2), WL(2), w[5],
                 nullptr, hh, hl, Csz, 256, 0, 1);
        run_gemm(hh, hl, NB, NB, NB, NB, WH(3), WL(3), w[7],
                 cmsg, nullptr, nullptr, Csz, 256, 0, 0);

        // l2l: MLP(flip(l)); flip fused via row^1
        run_gemm(lh, ll, NB, NB, NB, NB, WH(4), WL(4), w[9],
                 nullptr, hh, hl, Lsz, 256, 1, 1);
        run_gemm(hh, hl, NB, NB, NB, NB, WH(5), WL(5), w[11],
                 nullptr, t2h, t2l, Lsz, 256, 0, 0);

        // clause update
        cudaMemsetAsync(aggc, 0, (size_t)Csz * DD * sizeof(float), 0);
        scatter_add_kernel<<<scat_blocks, 256>>>((const float4*)lmsg, l_edge,
                                                 c_edge, (float4*)aggc, E);
        split_kernel<<<(Cn4 + 255) / 256, 256>>>((const float4*)aggc,
                                                 (uint2*)ach, (uint2*)acl, Cn4);
        run_gemm(chb, clb, ach, acl, NB, NB, WH(6), WL(6), w[13],
                 nullptr, hh, hl, Csz, 512, 0, 1);
        run_gemm(hh, hl, NB, NB, NB, NB, WH(7), WL(7), w[15],
                 c_out[t + 1], chb, clb, Csz, 256, 0, 0);

        // literal update
        cudaMemsetAsync(aggl, 0, (size_t)Lsz * DD * sizeof(float), 0);
        scatter_add_kernel<<<scat_blocks, 256>>>((const float4*)cmsg, c_edge,
                                                 l_edge, (float4*)aggl, E);
        split_kernel<<<(Ln4 + 255) / 256, 256>>>((const float4*)aggl,
                                                 (uint2*)alh, (uint2*)all_, Ln4);
        run_gemm(lh, ll, alh, all_, t2h, t2l, WH(8), WL(8), w[17],
                 nullptr, hh, hl, Lsz, 768, 0, 1);
        run_gemm(hh, hl, NB, NB, NB, NB, WH(9), WL(9), w[19],
                 l_out[t + 1], lh, ll, Lsz, 256, 0, 0);
    }
    #undef WH
    #undef WL
    #undef NB
}

// round 15
// speedup vs baseline: 1.4631x; 1.0264x over previous
#include <cuda_runtime.h>
#include <cuda_bf16.h>
#include <cstdint>

// ---------------------------------------------------------------------------
// GIN_LCG on GB300. Split-bf16 activations; tcgen05 3-term bf16 GEMMs, fp32
// TMEM acc, N=256 per CTA. Persistent grid=148, warp-specialized
// (warps 4-7 produce+issue, warps 0-3 epilogue), TMEM D ping-pong so the
// epilogue of tile t overlaps the MMAs of tile t+1.
// Output layout: l_embs [5][L][256] then c_embs [5][C][256], fp32.
// ---------------------------------------------------------------------------

#if defined(__CUDA_ARCH_FEAT_SM103_ALL) || defined(__CUDA_ARCH_FEAT_SM100_ALL) || \
    defined(__CUDA_ARCH_FEAT_SM101_ALL) || defined(__CUDA_ARCH_FEAT_SM110_ALL)
#define HAS_TC 1
#else
#define HAS_TC 0
#endif

#define DD 256
#define PAD_L 100096
#define PAD_C 50048

typedef __nv_bfloat16 bf16;

// -------------------- device scratch (no allocs allowed) -------------------
__device__ bf16 g_lh [(size_t)PAD_L * DD]; __device__ bf16 g_ll [(size_t)PAD_L * DD];
__device__ bf16 g_ch [(size_t)PAD_C * DD]; __device__ bf16 g_cl [(size_t)PAD_C * DD];
__device__ bf16 g_hh [(size_t)PAD_L * DD]; __device__ bf16 g_hl [(size_t)PAD_L * DD];
__device__ bf16 g_2h [(size_t)PAD_L * DD]; __device__ bf16 g_2l [(size_t)PAD_L * DD];
__device__ bf16 g_alh[(size_t)PAD_L * DD]; __device__ bf16 g_all[(size_t)PAD_L * DD];
__device__ bf16 g_ach[(size_t)PAD_C * DD]; __device__ bf16 g_acl[(size_t)PAD_C * DD];
__device__ float g_lmsg[(size_t)PAD_L * DD];
__device__ float g_cmsg[(size_t)PAD_C * DD];
__device__ float g_aggl[(size_t)PAD_L * DD];
__device__ float g_aggc[(size_t)PAD_C * DD];
__device__ bf16 g_wth[851968];
__device__ bf16 g_wtl[851968];

// -------------------- PTX helpers ------------------------------------------
__device__ __forceinline__ uint32_t smem_u32(const void* p) {
    uint32_t a;
    asm("{ .reg .u64 t; cvta.to.shared.u64 t, %1; cvt.u32.u64 %0, t; }"
        : "=r"(a) : "l"(p));
    return a;
}

#define FENCE_ASYNC()     asm volatile("fence.proxy.async.shared::cta;" ::: "memory")
#define MBAR_INIT(a, c) \
    asm volatile("mbarrier.init.shared.b64 [%0], %1;" :: "r"(a), "r"((uint32_t)(c)) : "memory")
#define MBAR_INVAL(a) \
    asm volatile("mbarrier.inval.shared.b64 [%0];" :: "r"(a) : "memory")
#define MBAR_ARRIVE(a) \
    asm volatile("mbarrier.arrive.shared.b64 _, [%0];" :: "r"(a) : "memory")
#define MBAR_WAIT(addr, ph) do {                                               \
    uint32_t _m = (addr); uint32_t _p = (ph);                                  \
    asm volatile("{\n\t.reg .pred P;\n\tWL_%=:\n\t"                            \
        "mbarrier.try_wait.parity.acquire.cta.shared::cta.b64 P, [%0], %1, 0x989680;\n\t" \
        "@P bra.uni WD_%=;\n\tbra.uni WL_%=;\n\tWD_%=:\n\t}"                   \
        :: "r"(_m), "r"(_p) : "memory");                                       \
} while (0)

#if HAS_TC
#define TC_ALLOC(sa, n) \
    asm volatile("tcgen05.alloc.cta_group::1.sync.aligned.shared::cta.b32 [%0], %1;" \
                 :: "r"(sa), "r"((uint32_t)(n)) : "memory")
#define TC_DEALLOC(t, n) \
    asm volatile("tcgen05.dealloc.cta_group::1.sync.aligned.b32 %0, %1;" \
                 :: "r"(t), "r"((uint32_t)(n)))
#define TC_RELINQ() \
    asm volatile("tcgen05.relinquish_alloc_permit.cta_group::1.sync.aligned;")
#define TC_COMMIT(mb) \
    asm volatile("tcgen05.commit.cta_group::1.mbarrier::arrive::one.shared::cluster.b64 [%0];" \
                 :: "r"(mb) : "memory")
#define TC_FENCE_AFTER()  asm volatile("tcgen05.fence::after_thread_sync;" ::: "memory")
#define TC_FENCE_BEFORE() asm volatile("tcgen05.fence::before_thread_sync;" ::: "memory")
#define TC_WAIT_LD()      asm volatile("tcgen05.wait::ld.sync.aligned;" ::: "memory")

#define TC_LD_X32(r, ta)                                                       \
    asm volatile("tcgen05.ld.sync.aligned.32x32b.x32.b32 "                     \
        "{%0, %1, %2, %3, %4, %5, %6, %7, "                                    \
        " %8, %9, %10, %11, %12, %13, %14, %15, "                              \
        " %16, %17, %18, %19, %20, %21, %22, %23, "                            \
        " %24, %25, %26, %27, %28, %29, %30, %31}, [%32];"                     \
        : "=r"((r)[0]),  "=r"((r)[1]),  "=r"((r)[2]),  "=r"((r)[3]),           \
          "=r"((r)[4]),  "=r"((r)[5]),  "=r"((r)[6]),  "=r"((r)[7]),           \
          "=r"((r)[8]),  "=r"((r)[9]),  "=r"((r)[10]), "=r"((r)[11]),          \
          "=r"((r)[12]), "=r"((r)[13]), "=r"((r)[14]), "=r"((r)[15]),          \
          "=r"((r)[16]), "=r"((r)[17]), "=r"((r)[18]), "=r"((r)[19]),          \
          "=r"((r)[20]), "=r"((r)[21]), "=r"((r)[22]), "=r"((r)[23]),          \
          "=r"((r)[24]), "=r"((r)[25]), "=r"((r)[26]), "=r"((r)[27]),          \
          "=r"((r)[28]), "=r"((r)[29]), "=r"((r)[30]), "=r"((r)[31])           \
        : "r"(ta))

__device__ __forceinline__ uint64_t smem_desc(uint32_t addr) {
    // SW128 K-major: layout=2, version=1(Blackwell), SBO=64, LBO=1
    const uint64_t base = (uint64_t(2) << 61) | (uint64_t(1) << 46) |
                          (uint64_t(64) << 32) | (uint64_t(1) << 16);
    return base | ((uint64_t)(addr >> 4) & 0x3FFF);
}
__device__ __forceinline__ void mma_f16_ss(uint32_t d, uint64_t ad, uint64_t bd,
                                           uint32_t idesc, bool accum) {
    uint32_t en = accum ? 1u : 0u;
    asm volatile(
        "{\n\t.reg .pred p;\n\tsetp.ne.u32 p, %5, 0;\n\t"
        "tcgen05.mma.cta_group::1.kind::f16 [%0], %1, %2, %3, {%4, %4, %4, %4}, p;\n\t}"
        :: "r"(d), "l"(ad), "l"(bd), "r"(idesc), "r"(0u), "r"(en) : "memory");
}
#endif  // HAS_TC

#define SW128(o) ((o) ^ ((((uint32_t)(o)) >> 3) & 0x70))

// idesc: dtype=F32, atype=btype=BF16, N=128, M=128 (cg1)  [proven]
static constexpr uint32_t IDESC =
    (1u << 4) | (1u << 7) | (1u << 10) | ((128u / 8) << 17) | ((128u / 16) << 24);

// stage: Ah 16K | Al 16K | Bh 32K | Bl 32K  = 96KB ; 2 stages
#define A_T         16384
#define B_T         32768
#define STAGE_BYTES (2 * A_T + 2 * B_T)
#define SMEM_TOTAL  (1024 + 2 * STAGE_BYTES)

// mbarrier offsets in ctrl region: stage0 +8, stage1 +16, tile0 +24, tile1 +32,
// dfree0 +40, dfree1 +48
#define MB_STAGE(sb, b) ((sb) + ((b) ? 16 : 8))
#define MB_TILE(sb, q)  ((sb) + ((q) ? 32 : 24))
#define MB_DFREE(sb, q) ((sb) + ((q) ? 48 : 40))

struct GemmParams {
    const bf16 *A0h, *A0l, *A1h, *A1l, *A2h, *A2l;  // [M,256] row-major K-segments
    const bf16 *Wh, *Wl;                             // [256, K]
    const float* bias;
    float* C;                                        // optional fp32 out
    bf16 *Ch, *Cl;                                   // optional split bf16 out
    int M, K, row_xor, relu;
};

__device__ __forceinline__ uint32_t pkbf(bf16 a, bf16 b) {
    __nv_bfloat162 t(a, b);
    return *reinterpret_cast<uint32_t*>(&t);
}

#if HAS_TC
// 128-thread coalesced stage producer (8 lanes per 128B row-slice).
__device__ __forceinline__ void produce_stage128(
    const GemmParams& p, char* tb, uint32_t sb, int buf, int s,
    int rowBase, int ptid, int wait_cnt) {

    const int k0  = s * 64;
    const int seg = k0 >> 8;
    const bf16* Ah = (seg == 0) ? p.A0h : ((seg == 1) ? p.A1h : p.A2h);
    const bf16* Al = (seg == 0) ? p.A0l : ((seg == 1) ? p.A1l : p.A2l);
    const int kc = k0 & 255;

    // A: 1024 16B-units per part; 8 per thread per part.
    uint4 ah[8], al[8];
    #pragma unroll
    for (int it = 0; it < 8; it++) {
        const int idx = ptid + it * 128;
        const int r = idx >> 3, j = idx & 7;
        const size_t go = (size_t)((rowBase + r) ^ p.row_xor) * DD + kc + j * 8;
        ah[it] = __ldg((const uint4*)(Ah + go));
        al[it] = __ldg((const uint4*)(Al + go));
    }

    if (wait_cnt > 0)
        MBAR_WAIT(MB_STAGE(sb, buf), (uint32_t)((wait_cnt - 1) & 1));

    #pragma unroll
    for (int it = 0; it < 8; it++) {
        const int idx = ptid + it * 128;
        const int r = idx >> 3, j = idx & 7;
        const uint32_t so = SW128((uint32_t)(r * 128 + j * 16));
        *(uint4*)(tb + so)       = ah[it];
        *(uint4*)(tb + A_T + so) = al[it];
    }

    // B: 2048 16B-units per part; 16 per thread per part, in batches of 8.
    #pragma unroll
    for (int half = 0; half < 2; half++) {
        uint4 bv[8];
        #pragma unroll
        for (int it = 0; it < 8; it++) {
            const int idx = ptid + (half * 8 + it) * 128;
            const int n = idx >> 3, j = idx & 7;
            bv[it] = __ldg((const uint4*)(p.Wh + (size_t)n * p.K + k0 + j * 8));
        }
        #pragma unroll
        for (int it = 0; it < 8; it++) {
            const int idx = ptid + (half * 8 + it) * 128;
            const int n = idx >> 3, j = idx & 7;
            const uint32_t so = SW128((uint32_t)(n * 128 + j * 16));
            *(uint4*)(tb + 2 * A_T + so) = bv[it];
        }
    }
    #pragma unroll
    for (int half = 0; half < 2; half++) {
        uint4 bv[8];
        #pragma unroll
        for (int it = 0; it < 8; it++) {
            const int idx = ptid + (half * 8 + it) * 128;
            const int n = idx >> 3, j = idx & 7;
            bv[it] = __ldg((const uint4*)(p.Wl + (size_t)n * p.K + k0 + j * 8));
        }
        #pragma unroll
        for (int it = 0; it < 8; it++) {
            const int idx = ptid + (half * 8 + it) * 128;
            const int n = idx >> 3, j = idx & 7;
            const uint32_t so = SW128((uint32_t)(n * 128 + j * 16));
            *(uint4*)(tb + 2 * A_T + B_T + so) = bv[it];
        }
    }
    FENCE_ASYNC();
}
#endif  // HAS_TC

__global__ __launch_bounds__(256, 1)
void gemm_tc(GemmParams p) {
#if HAS_TC
    extern __shared__ char smem[];
    const uint32_t sb = smem_u32(smem);
    const uint32_t tbase = (sb + 64 + 1023u) & ~1023u;
    char* tilep = smem + (tbase - sb);
    const int tid = threadIdx.x;
    const int wid = tid >> 5, lid = tid & 31;
    const int ntiles = (p.M + 127) >> 7;
    const int nst = p.K >> 6;

    if (wid == 4) TC_ALLOC(sb, 512);
    if (tid == 0) {
        MBAR_INIT(sb + 8, 1);   MBAR_INIT(sb + 16, 1);    // stage commits
        MBAR_INIT(sb + 24, 1);  MBAR_INIT(sb + 32, 1);    // tile-done commits
        MBAR_INIT(sb + 40, 128); MBAR_INIT(sb + 48, 128); // D-free (epi arrives)
    }
    __syncthreads();
    uint32_t tmem;
    asm volatile("ld.shared.b32 %0, [%1];" : "=r"(tmem) : "r"(sb));

    if (tid >= 128) {
        // ---------------- producer + MMA-issue group (warps 4-7) ----------
        const int ptid = tid - 128;
        int scnt[2] = {0, 0};
        int sg = 0;
        int tcnt = 0;
        for (int tile = blockIdx.x; tile < ntiles; tile += gridDim.x, tcnt++) {
            const int q = tcnt & 1;
            const int rowBase = tile << 7;
            for (int s = 0; s < nst; s++) {
                const int buf = sg & 1;
                produce_stage128(p, tilep + buf * STAGE_BYTES, sb, buf, s,
                                 rowBase, ptid, scnt[buf]);
                asm volatile("bar.sync 1, 128;" ::: "memory");
                if (tid == 128) {
                    if (s == 0 && tcnt >= 2)
                        MBAR_WAIT(MB_DFREE(sb, q),
                                  (uint32_t)(((tcnt >> 1) - 1) & 1));
                    const uint32_t tb32 = tbase + buf * STAGE_BYTES;
                    const uint64_t dah = smem_desc(tb32);
                    const uint64_t dal = smem_desc(tb32 + A_T);
                    const uint64_t dbh = smem_desc(tb32 + 2 * A_T);
                    const uint64_t dbl = smem_desc(tb32 + 2 * A_T + B_T);
                    #pragma unroll
                    for (int n = 0; n < 2; n++) {
                        const uint32_t d  = tmem + q * 256 + n * 128;
                        const uint64_t bh = dbh + n * 1024;
                        const uint64_t bl = dbl + n * 1024;
                        #pragma unroll
                        for (int sub = 0; sub < 4; sub++) {
                            const bool first = (s == 0 && sub == 0);
                            mma_f16_ss(d, dah + sub * 2, bh + sub * 2, IDESC, !first);
                            mma_f16_ss(d, dah + sub * 2, bl + sub * 2, IDESC, true);
                            mma_f16_ss(d, dal + sub * 2, bh + sub * 2, IDESC, true);
                        }
                    }
                    TC_COMMIT(MB_STAGE(sb, buf));
                    if (s == nst - 1) TC_COMMIT(MB_TILE(sb, q));
                }
                scnt[buf]++; sg++;
            }
        }
    } else {
        // ---------------- epilogue group (warps 0-3) -----------------------
        int tcnt = 0;
        for (int tile = blockIdx.x; tile < ntiles; tile += gridDim.x, tcnt++) {
            const int q = tcnt & 1;
            const int rowBase = tile << 7;
            MBAR_WAIT(MB_TILE(sb, q), (uint32_t)((tcnt >> 1) & 1));
            TC_FENCE_AFTER();

            const int rr = rowBase + wid * 32 + lid;
            const bool v = rr < p.M;
            float* crow = p.C  ? p.C  + (size_t)rr * DD : nullptr;
            bf16*  hrow = p.Ch ? p.Ch + (size_t)rr * DD : nullptr;
            bf16*  lrow = p.Cl ? p.Cl + (size_t)rr * DD : nullptr;
            #pragma unroll
            for (int ch = 0; ch < 8; ch++) {
                uint32_t dr[32];
                TC_LD_X32(dr, tmem + q * 256 + ch * 32);
                TC_WAIT_LD();
                if (v) {
                    #pragma unroll
                    for (int j = 0; j < 8; j++) {
                        const int c = ch * 32 + j * 4;
                        float4 o;
                        o.x = __uint_as_float(dr[j * 4 + 0]) + __ldg(&p.bias[c + 0]);
                        o.y = __uint_as_float(dr[j * 4 + 1]) + __ldg(&p.bias[c + 1]);
                        o.z = __uint_as_float(dr[j * 4 + 2]) + __ldg(&p.bias[c + 2]);
                        o.w = __uint_as_float(dr[j * 4 + 3]) + __ldg(&p.bias[c + 3]);
                        if (p.relu) {
                            o.x = fmaxf(o.x, 0.f); o.y = fmaxf(o.y, 0.f);
                            o.z = fmaxf(o.z, 0.f); o.w = fmaxf(o.w, 0.f);
                        }
                        if (crow) *(float4*)(crow + c) = o;
                        if (hrow) {
                            bf16 h0 = __float2bfloat16_rn(o.x);
                            bf16 h1 = __float2bfloat16_rn(o.y);
                            bf16 h2 = __float2bfloat16_rn(o.z);
                            bf16 h3 = __float2bfloat16_rn(o.w);
                            uint2 hv, lv;
                            hv.x = pkbf(h0, h1); hv.y = pkbf(h2, h3);
                            lv.x = pkbf(__float2bfloat16_rn(o.x - __bfloat162float(h0)),
                                        __float2bfloat16_rn(o.y - __bfloat162float(h1)));
                            lv.y = pkbf(__float2bfloat16_rn(o.z - __bfloat162float(h2)),
                                        __float2bfloat16_rn(o.w - __bfloat162float(h3)));
                            *(uint2*)(hrow + c) = hv;
                            *(uint2*)(lrow + c) = lv;
                        }
                    }
                }
            }
            TC_FENCE_BEFORE();
            MBAR_ARRIVE(MB_DFREE(sb, q));
        }
    }

    __syncthreads();
    if (tid == 0) {
        MBAR_INVAL(sb + 8);  MBAR_INVAL(sb + 16);
        MBAR_INVAL(sb + 24); MBAR_INVAL(sb + 32);
        MBAR_INVAL(sb + 40); MBAR_INVAL(sb + 48);
    }
    __syncthreads();
    if (wid == 4) { TC_RELINQ(); TC_DEALLOC(tmem, 512); }

#else  // ---------------- fp32 SIMT fallback (base-arch cubin; safety) -------
    __shared__ float As[16][132];
    __shared__ float Bs[16][128];
    const int tid = threadIdx.x;
    const int tx  = tid & 15;
    const int ty  = tid >> 4;
    const int ntiles = (p.M + 127) >> 7;

    for (int tile = blockIdx.x; tile < ntiles; tile += gridDim.x) {
        const int rowBase = tile << 7;
        for (int nh = 0; nh < 2; nh++) {
            const int colBase = nh * 128;
            float acc[8][8];
            #pragma unroll
            for (int i = 0; i < 8; i++)
                #pragma unroll
                for (int j = 0; j < 8; j++) acc[i][j] = 0.f;

            const int nt = p.K / 16;
            const int a_row = tid >> 2, a_c4 = tid & 3;
            const int b_n = tid >> 1, b_h = tid & 1;

            for (int t = 0; t < nt; t++) {
                const int k0 = t * 16, seg = k0 >> 8;
                const bf16* Ah = (seg == 0) ? p.A0h : ((seg == 1) ? p.A1h : p.A2h);
                const bf16* Al = (seg == 0) ? p.A0l : ((seg == 1) ? p.A1l : p.A2l);
                const int kcol = (k0 & 255) + a_c4 * 4;
                #pragma unroll
                for (int i = 0; i < 2; i++) {
                    const int r = rowBase + a_row + i * 64;
                    const size_t ro = (size_t)((r < p.M ? r : 0) ^ p.row_xor) * DD + kcol;
                    #pragma unroll
                    for (int q = 0; q < 4; q++)
                        As[a_c4 * 4 + q][a_row + i * 64] =
                            (r < p.M) ? __bfloat162float(Ah[ro + q]) +
                                        __bfloat162float(Al[ro + q]) : 0.f;
                }
                {
                    const size_t wo = (size_t)(colBase + b_n) * p.K + k0 + b_h * 8;
                    #pragma unroll
                    for (int j = 0; j < 8; j++)
                        Bs[b_h * 8 + j][b_n] = __bfloat162float(p.Wh[wo + j]) +
                                               __bfloat162float(p.Wl[wo + j]);
                }
                __syncthreads();
                #pragma unroll
                for (int k = 0; k < 16; k++) {
                    float a[8], b[8];
                    #pragma unroll
                    for (int i = 0; i < 8; i++) a[i] = As[k][ty * 8 + i];
                    #pragma unroll
                    for (int j = 0; j < 8; j++) b[j] = Bs[k][tx * 8 + j];
                    #pragma unroll
                    for (int i = 0; i < 8; i++)
                        #pragma unroll
                        for (int j = 0; j < 8; j++)
                            acc[i][j] = fmaf(a[i], b[j], acc[i][j]);
                }
                __syncthreads();
            }

            const int col = colBase + tx * 8;
            #pragma unroll
            for (int i = 0; i < 8; i++) {
                const int r = rowBase + ty * 8 + i;
                if (r >= p.M) break;
                #pragma unroll
                for (int j = 0; j < 8; j++) {
                    float o = acc[i][j] + p.bias[col + j];
                    if (p.relu) o = fmaxf(o, 0.f);
                    if (p.C) p.C[(size_t)r * DD + col + j] = o;
                    if (p.Ch) {
                        bf16 h = __float2bfloat16_rn(o);
                        p.Ch[(size_t)r * DD + col + j] = h;
                        p.Cl[(size_t)r * DD + col + j] =
                            __float2bfloat16_rn(o - __bfloat162float(h));
                    }
                }
            }
            __syncthreads();
        }
    }
#endif
}

// -------------------- weight transpose + bf16 split ------------------------
__global__ void wsplit_kernel(const float* __restrict__ W,
                              bf16* __restrict__ oh, bf16* __restrict__ ol,
                              int K, int N) {
    const int idx = blockIdx.x * blockDim.x + threadIdx.x;
    if (idx >= K * N) return;
    const int n = idx / K;
    const int k = idx - n * K;
    const float x = W[(size_t)k * N + n];
    const bf16 hi = __float2bfloat16_rn(x);
    oh[idx] = hi;
    ol[idx] = __float2bfloat16_rn(x - __bfloat162float(hi));
}

// -------------------- fp32 -> split bf16 (elementwise) ---------------------
__global__ void split_kernel(const float4* __restrict__ in,
                             uint2* __restrict__ oh, uint2* __restrict__ ol,
                             int n4) {
    const int i = blockIdx.x * blockDim.x + threadIdx.x;
    if (i >= n4) return;
    const float4 v = __ldg(&in[i]);
    const bf16 h0 = __float2bfloat16_rn(v.x);
    const bf16 h1 = __float2bfloat16_rn(v.y);
    const bf16 h2 = __float2bfloat16_rn(v.z);
    const bf16 h3 = __float2bfloat16_rn(v.w);
    uint2 hv, lv;
    __nv_bfloat162 a(h0, h1), b(h2, h3);
    hv.x = *reinterpret_cast<uint32_t*>(&a);
    hv.y = *reinterpret_cast<uint32_t*>(&b);
    __nv_bfloat162 c(__float2bfloat16_rn(v.x - __bfloat162float(h0)),
                     __float2bfloat16_rn(v.y - __bfloat162float(h1)));
    __nv_bfloat162 d(__float2bfloat16_rn(v.z - __bfloat162float(h2)),
                     __float2bfloat16_rn(v.w - __bfloat162float(h3)));
    lv.x = *reinterpret_cast<uint32_t*>(&c);
    lv.y = *reinterpret_cast<uint32_t*>(&d);
    oh[i] = hv;
    ol[i] = lv;
}

// -------------------- fused gather + segment-sum over edges ----------------
__global__ void scatter_add_kernel(const float4* __restrict__ msg,
                                   const int* __restrict__ src,
                                   const int* __restrict__ dst,
                                   float4* __restrict__ aggr, int E) {
    int t = blockIdx.x * blockDim.x + threadIdx.x;
    const int total = E * (DD / 4);
    if (t >= total) return;
    const int e = t >> 6;
    const int c = t & 63;
    const int s = __ldg(&src[e]);
    const int d = __ldg(&dst[e]);
    float4 v = __ldg(&msg[(size_t)s * 64 + c]);
    float4* p = &aggr[(size_t)d * 64 + c];
    asm volatile("red.global.add.v4.f32 [%0], {%1, %2, %3, %4};"
                 :: "l"(p), "f"(v.x), "f"(v.y), "f"(v.z), "f"(v.w)
                 : "memory");
}

// -------------------- host orchestration -----------------------------------
static void run_gemm(const bf16* A0h, const bf16* A0l,
                     const bf16* A1h, const bf16* A1l,
                     const bf16* A2h, const bf16* A2l,
                     const bf16* Wh, const bf16* Wl, const float* bias,
                     float* C, bf16* Ch, bf16* Cl,
                     int M, int K, int row_xor, int relu) {
    GemmParams p;
    p.A0h = A0h; p.A0l = A0l; p.A1h = A1h; p.A1l = A1l; p.A2h = A2h; p.A2l = A2l;
    p.Wh = Wh; p.Wl = Wl; p.bias = bias;
    p.C = C; p.Ch = Ch; p.Cl = Cl;
    p.M = M; p.K = K; p.row_xor = row_xor; p.relu = relu;
    gemm_tc<<<148, 256, SMEM_TOTAL>>>(p);
}

extern "C" void kernel_launch(void* const* d_in, const int* in_sizes, int n_in,
                              void* d_out, int out_size) {
    const int off = n_in - 24;
    const int*   l_edge = (const int*)  d_in[off + 0];
    const int*   c_edge = (const int*)  d_in[off + 1];
    const float* l_emb0 = (const float*)d_in[off + 2];
    const float* c_emb0 = (const float*)d_in[off + 3];
    const float* w[20];
    for (int i = 0; i < 20; i++) w[i] = (const float*)d_in[off + 4 + i];
    // w[0..3]=l2c, w[4..7]=c2l, w[8..11]=l2l, w[12..15]=cu, w[16..19]=lu

    const int E   = in_sizes[off + 0];
    const int Lsz = in_sizes[off + 2] / DD;
    const int Csz = in_sizes[off + 3] / DD;

    bf16 *lh, *ll, *chb, *clb, *hh, *hl, *t2h, *t2l, *alh, *all_, *ach, *acl;
    cudaGetSymbolAddress((void**)&lh,  g_lh);  cudaGetSymbolAddress((void**)&ll,  g_ll);
    cudaGetSymbolAddress((void**)&chb, g_ch);  cudaGetSymbolAddress((void**)&clb, g_cl);
    cudaGetSymbolAddress((void**)&hh,  g_hh);  cudaGetSymbolAddress((void**)&hl,  g_hl);
    cudaGetSymbolAddress((void**)&t2h, g_2h);  cudaGetSymbolAddress((void**)&t2l, g_2l);
    cudaGetSymbolAddress((void**)&alh, g_alh); cudaGetSymbolAddress((void**)&all_, g_all);
    cudaGetSymbolAddress((void**)&ach, g_ach); cudaGetSymbolAddress((void**)&acl, g_acl);
    float *lmsg, *cmsg, *aggl, *aggc;
    cudaGetSymbolAddress((void**)&lmsg, g_lmsg);
    cudaGetSymbolAddress((void**)&cmsg, g_cmsg);
    cudaGetSymbolAddress((void**)&aggl, g_aggl);
    cudaGetSymbolAddress((void**)&aggc, g_aggc);
    bf16 *wth, *wtl;
    cudaGetSymbolAddress((void**)&wth, g_wth);
    cudaGetSymbolAddress((void**)&wtl, g_wtl);

    cudaFuncSetAttribute(gemm_tc, cudaFuncAttributeMaxDynamicSharedMemorySize,
                         SMEM_TOTAL);

    // transpose + split the 10 weight matrices into bf16 hi/lo [256, K]
    static const size_t woff[10] = {0, 65536, 131072, 196608, 262144, 327680,
                                    393216, 524288, 589824, 786432};
    static const int    wKs [10] = {256, 256, 256, 256, 256, 256, 512, 256, 768, 256};
    static const int    wsrc[10] = {0, 2, 4, 6, 8, 10, 12, 14, 16, 18};
    for (int i = 0; i < 10; i++) {
        const int total = wKs[i] * 256;
        wsplit_kernel<<<(total + 255) / 256, 256>>>(w[wsrc[i]], wth + woff[i],
                                                    wtl + woff[i], wKs[i], 256);
    }

    float* out = (float*)d_out;
    float* l_out[5];
    float* c_out[5];
    for (int t = 0; t < 5; t++) {
        l_out[t] = out + (size_t)t * Lsz * DD;
        c_out[t] = out + (size_t)5 * Lsz * DD + (size_t)t * Csz * DD;
    }

    cudaMemcpyAsync(l_out[0], l_emb0, (size_t)Lsz * DD * sizeof(float),
                    cudaMemcpyDeviceToDevice, 0);
    cudaMemcpyAsync(c_out[0], c_emb0, (size_t)Csz * DD * sizeof(float),
                    cudaMemcpyDeviceToDevice, 0);

    const int Ln4 = Lsz * DD / 4, Cn4 = Csz * DD / 4;
    split_kernel<<<(Ln4 + 255) / 256, 256>>>((const float4*)l_emb0,
                                             (uint2*)lh, (uint2*)ll, Ln4);
    split_kernel<<<(Cn4 + 255) / 256, 256>>>((const float4*)c_emb0,
                                             (uint2*)chb, (uint2*)clb, Cn4);

    const int scat_total  = E * (DD / 4);
    const int scat_blocks = (scat_total + 255) / 256;

    #define WH(i) (wth + woff[i])
    #define WL(i) (wtl + woff[i])
    #define NB    (const bf16*)nullptr

    for (int t = 0; t < 4; t++) {
        // l2c message features
        run_gemm(lh, ll, NB, NB, NB, NB, WH(0), WL(0), w[1],
                 nullptr, hh, hl, Lsz, 256, 0, 1);
        run_gemm(hh, hl, NB, NB, NB, NB, WH(1), WL(1), w[3],
                 lmsg, nullptr, nullptr, Lsz, 256, 0, 0);

        // c2l message features
        run_gemm(chb, clb, NB, NB, NB, NB, WH(2), WL(2), w[5],
                 nullptr, hh, hl, Csz, 256, 0, 1);
        run_gemm(hh, hl, NB, NB, NB, NB, WH(3), WL(3), w[7],
                 cmsg, nullptr, nullptr, Csz, 256, 0, 0);

        // l2l: MLP(flip(l)); flip fused via row^1
        run_gemm(lh, ll, NB, NB, NB, NB, WH(4), WL(4), w[9],
                 nullptr, hh, hl, Lsz, 256, 1, 1);
        run_gemm(hh, hl, NB, NB, NB, NB, WH(5), WL(5), w[11],
                 nullptr, t2h, t2l, Lsz, 256, 0, 0);

        // clause update
        cudaMemsetAsync(aggc, 0, (size_t)Csz * DD * sizeof(float), 0);
        scatter_add_kernel<<<scat_blocks, 256>>>((const float4*)lmsg, l_edge,
                                                 c_edge, (float4*)aggc, E);
        split_kernel<<<(Cn4 + 255) / 256, 256>>>((const float4*)aggc,
                                                 (uint2*)ach, (uint2*)acl, Cn4);
        run_gemm(chb, clb, ach, acl, NB, NB, WH(6), WL(6), w[13],
                 nullptr, hh, hl, Csz, 512, 0, 1);
        run_gemm(hh, hl, NB, NB, NB, NB, WH(7), WL(7), w[15],
                 c_out[t + 1], chb, clb, Csz, 256, 0, 0);

        // literal update
        cudaMemsetAsync(aggl, 0, (size_t)Lsz * DD * sizeof(float), 0);
        scatter_add_kernel<<<scat_blocks, 256>>>((const float4*)cmsg, c_edge,
                                                 l_edge, (float4*)aggl, E);
        split_kernel<<<(Ln4 + 255) / 256, 256>>>((const float4*)aggl,
                                                 (uint2*)alh, (uint2*)all_, Ln4);
        run_gemm(lh, ll, alh, all_, t2h, t2l, WH(8), WL(8), w[17],
                 nullptr, hh, hl, Lsz, 768, 0, 1);
        run_gemm(hh, hl, NB, NB, NB, NB, WH(9), WL(9), w[19],
                 l_out[t + 1], lh, ll, Lsz, 256, 0, 0);
    }
    #undef WH
    #undef WL
    #undef NB
}